// round 5
// baseline (speedup 1.0000x reference)
#include <cuda_runtime.h>
#include <cuda_fp16.h>

// Non-local means, 4 x 1 x 1024 x 1024 fp32.
// h = 7/255, template 7x7, search 21x21, reflect-101 padding everywhere.
//
// Per-CTA SMEM tile stores x[refl(g)] indexed by unreflected global coords
// (halo 13 = 10 search + 3 box). Vertical 7-box: register sliding window.
// Horizontal 7-box: warp-shuffle tree on half2-packed PAIRS of rows.
// exp scale folded into the diff so the weight is a single ex2.approx.
//
// R4 addition: log-domain early rejection. V(lane) = -K*log2e * (vertical
// 7-sum of diff^2) <= 0, and s7 = sum of 7 lane-V's <= each V. If ALL lanes
// of a 4-row quad have V < -25, every weight in the quad is < 2^-25
// (reference fp32 exp underflows these to 0 anyway) -> skip the entire
// shuffle/ex2/accumulate tail via one warp vote. Error bound 441*2^-25~1e-5.

static constexpr int IMG_H = 1024;
static constexpr int IMG_W = 1024;
static constexpr int OUT_H = 32;     // CTA output rows
static constexpr int OUT_W = 104;    // CTA output cols = 4 warps * 26
static constexpr int REG_H = OUT_H + 26;   // 58
static constexpr int REG_W = OUT_W + 26;   // 130
static constexpr int NTHREADS = 256;

// dist/h^2 = boxsum/49 * (255/7)^2 = boxsum * 65025/2401 = K
// w = exp(-K*boxsum) = 2^(-K*log2e*boxsum);  C2 = K*log2e, SC = sqrt(C2)
static constexpr float SC = 6.2507390f;
static constexpr float VTH = -25.0f;   // skip threshold in log2 domain

__device__ __forceinline__ int refl(int g, int n) {
    g = (g < 0) ? -g : g;
    return (g >= n) ? (2 * n - 2 - g) : g;
}

__device__ __forceinline__ float ex2(float x) {
    float r;
    asm("ex2.approx.ftz.f32 %0, %1;" : "=f"(r) : "f"(x));
    return r;
}

// Per-warp accumulation over all 441 offsets.
// RB: apply row reflection for the outer (box) halo (edge row-strips only).
template <bool RB>
__device__ __forceinline__ void nlm_accum(
    const float* __restrict__ S,     // SMEM region
    const float* __restrict__ Cc,    // center column * SC, 22 values
    float (&wacc)[16], float (&vacc)[16],
    int rw0,        // warp's first output row (global)
    int r0m13,      // r0 - 13 (SMEM row origin, global coords)
    int colB,       // SMEM col of this thread's (reflected) V-column
    int colS)       // SMEM col of this thread's output pixel (lane-clamped)
{
    #pragma unroll 1
    for (int dy = -10; dy <= 10; ++dy) {
        #pragma unroll 1
        for (int dx = -10; dx <= 10; ++dx) {
            const int cb = colB + dx;
            const int cs = colS + dx;
            float d[7];
            float V = 0.0f;
            // warm-up: rows j = rw0-3 .. rw0+2
            #pragma unroll
            for (int m = 0; m < 6; ++m) {
                int j = rw0 - 3 + m;
                int qr = RB ? refl(j, IMG_H) : j;
                float bv = S[(qr + dy - r0m13) * REG_W + cb];
                float t = fmaf(-SC, bv, Cc[m]);
                d[m] = -t * t;
                V += d[m];
            }
            // main: 4 quads of 4 rows each; V = -C2 * (7-row vertical sum)
            #pragma unroll
            for (int q = 0; q < 4; ++q) {
                float Vq[4];
                #pragma unroll
                for (int s = 0; s < 4; ++s) {
                    int i = 4 * q + s;
                    int j = rw0 + 3 + i;
                    int qr = RB ? refl(j, IMG_H) : j;
                    float bv = S[(qr + dy - r0m13) * REG_W + cb];
                    float t = fmaf(-SC, bv, Cc[i + 6]);
                    float dn = -t * t;
                    V += dn;
                    d[(i + 6) % 7] = dn;
                    Vq[s] = V;
                    V -= d[i % 7];
                }
                // log-domain rejection: if every lane's V < VTH for all 4
                // rows, every s7 in this quad is < VTH -> weights < 2^-25.
                float vmax = fmaxf(fmaxf(Vq[0], Vq[1]), fmaxf(Vq[2], Vq[3]));
                if (__any_sync(0xffffffffu, vmax >= VTH)) {
                    int i = 4 * q;
                    // horizontal 7-sums for 4 rows, packed as two half2:
                    __half2 hA = __floats2half2_rn(Vq[0], Vq[1]);
                    __half2 hB = __floats2half2_rn(Vq[2], Vq[3]);
                    __half2 aA = __hadd2(hA, __shfl_down_sync(0xffffffffu, hA, 1));
                    __half2 aB = __hadd2(hB, __shfl_down_sync(0xffffffffu, hB, 1));
                    __half2 bA = __hadd2(aA, __shfl_down_sync(0xffffffffu, aA, 2));
                    __half2 bB = __hadd2(aB, __shfl_down_sync(0xffffffffu, aB, 2));
                    __half2 sA = __hadd2(bA,
                                 __hadd2(__shfl_down_sync(0xffffffffu, aA, 4),
                                         __shfl_down_sync(0xffffffffu, hA, 6)));
                    __half2 sB = __hadd2(bB,
                                 __hadd2(__shfl_down_sync(0xffffffffu, aB, 4),
                                         __shfl_down_sync(0xffffffffu, hB, 6)));
                    float w0 = ex2(__low2float(sA));
                    float w1 = ex2(__high2float(sA));
                    float w2 = ex2(__low2float(sB));
                    float w3 = ex2(__high2float(sB));
                    const float* Srow = S + (rw0 + i + dy - r0m13) * REG_W + cs;
                    float sh0 = Srow[0];
                    float sh1 = Srow[REG_W];
                    float sh2 = Srow[2 * REG_W];
                    float sh3 = Srow[3 * REG_W];
                    wacc[i]     += w0;  vacc[i]     = fmaf(w0, sh0, vacc[i]);
                    wacc[i + 1] += w1;  vacc[i + 1] = fmaf(w1, sh1, vacc[i + 1]);
                    wacc[i + 2] += w2;  vacc[i + 2] = fmaf(w2, sh2, vacc[i + 2]);
                    wacc[i + 3] += w3;  vacc[i + 3] = fmaf(w3, sh3, vacc[i + 3]);
                }
            }
        }
    }
}

__global__ __launch_bounds__(NTHREADS, 2)
void nlm_kernel(const float* __restrict__ x, float* __restrict__ out) {
    __shared__ float S[REG_H * REG_W];

    const int b  = blockIdx.z;
    const int r0 = blockIdx.y * OUT_H;
    const int c0 = blockIdx.x * OUT_W;
    const int tid = threadIdx.x;

    // Load reflect-padded region: S[(gr-(r0-13))*REG_W + (gc-(c0-13))] = x[refl(g)]
    const float* xb = x + (size_t)b * (IMG_H * IMG_W);
    #pragma unroll 4
    for (int idx = tid; idx < REG_H * REG_W; idx += NTHREADS) {
        int i = idx / REG_W;
        int j = idx - i * REG_W;
        int gr = refl(r0 - 13 + i, IMG_H);
        int gc = refl(c0 - 13 + j, IMG_W);
        S[idx] = xb[gr * IMG_W + gc];
    }
    __syncthreads();

    const int w = tid >> 5, l = tid & 31;
    const int wx = w & 3, wy = w >> 2;
    const int rw0 = r0 + wy * 16;        // warp's first output row
    const int c0w = c0 + wx * 26;        // warp's first output col
    const int u = c0w - 3 + l;           // this lane's V column (unreflected)
    const int qc = refl(u, IMG_W);       // reflected column (fixed per thread)
    const int r0m13 = r0 - 13;
    const int c0m13 = c0 - 13;
    const int colB = qc - c0m13;
    const int lclamp = (l < 26) ? l : 25;
    const int colS = (c0w + lclamp) - c0m13;

    // Center column cache, pre-scaled: Cc[m] = SC * x(refl(rw0-3+m), qc)
    float Cc[22];
    #pragma unroll
    for (int m = 0; m < 22; ++m) {
        int qr = refl(rw0 - 3 + m, IMG_H);
        Cc[m] = SC * S[(qr - r0m13) * REG_W + colB];
    }

    float wacc[16], vacc[16];
    #pragma unroll
    for (int i = 0; i < 16; ++i) { wacc[i] = 0.0f; vacc[i] = 0.0f; }

    const bool rowRefl = (rw0 - 3 < 0) || (rw0 + 18 >= IMG_H);
    if (!rowRefl) {
        nlm_accum<false>(S, Cc, wacc, vacc, rw0, r0m13, colB, colS);
    } else {
        nlm_accum<true>(S, Cc, wacc, vacc, rw0, r0m13, colB, colS);
    }

    // Write out: lanes 0..25 hold valid outputs
    const int cout = c0w + l;
    if (l < 26 && cout < IMG_W) {
        float* ob = out + (size_t)b * (IMG_H * IMG_W);
        #pragma unroll
        for (int i = 0; i < 16; ++i) {
            float q = vacc[i] / wacc[i];
            q = fminf(fmaxf(q, 0.0f), 1.0f);
            ob[(rw0 + i) * IMG_W + cout] = q;
        }
    }
}

extern "C" void kernel_launch(void* const* d_in, const int* in_sizes, int n_in,
                              void* d_out, int out_size) {
    const float* x = (const float*)d_in[0];
    float* out = (float*)d_out;
    (void)in_sizes; (void)n_in; (void)out_size;

    dim3 grid((IMG_W + OUT_W - 1) / OUT_W,   // 10
              IMG_H / OUT_H,                 // 32
              4);                            // batch
    dim3 block(NTHREADS);
    nlm_kernel<<<grid, block>>>(x, out);
}

// round 7
// speedup vs baseline: 2.3555x; 2.3555x over previous
#include <cuda_runtime.h>
#include <cuda_fp16.h>

// Non-local means, 4 x 1 x 1024 x 1024 fp32.
// h = 7/255, template 7x7, search 21x21, reflect-101 padding.
//
// Two SMEM tiles indexed by unreflected global coords (halo 13):
//   Sf : fp32 reflect-padded values (for tail/epilogue exactness)
//   S2 : half2 pairs S2[j] = (half(x[j]), half(x[j+1])) -> one LDS.32 serves
//        TWO search offsets (dx, dx+1); whole diff pipeline runs in half2.
// Vertical 7-box: half2 register sliding window (ring of 7).
// Early rejection: weight(l) = exp(-K*s7(l)), s7 = sum of 7 lane V's >= each
// V >= 0. Non-negligible weight needs ALL 7 window lanes V <= TH. Ballot the
// per-quad min, test for a 7-consecutive-bit run; no run -> every weight in
// the quad (both dx) is < 2^-25 -> skip the shuffle/ex2/accumulate tail.
// Error bound 441 * 2^-25 ~ 1.3e-5 (reference fp32 exp underflows these to 0).

static constexpr int IMG_H = 1024;
static constexpr int IMG_W = 1024;
static constexpr int OUT_H = 32;
static constexpr int OUT_W = 104;          // 4 warps * 26
static constexpr int REG_H = OUT_H + 26;   // 58
static constexpr int REG_W = OUT_W + 26;   // 130
static constexpr int NTHREADS = 256;
static constexpr int TILE_N = REG_H * REG_W;            // 7540
static constexpr int SMEM_BYTES = TILE_N * 4 * 2;       // fp32 + half2 tiles

// dist/h^2 = S49 * 65025/2401 = K*S49 ; weight = 2^(-C2*S49), C2 = K*log2e
static constexpr float C2F = 39.07174f;
// skip-safe: s7raw > 25/C2 = 0.6399 -> w < 2^-25. Margin for half rounding.
static constexpr float THR = 0.66f;

__device__ __forceinline__ int refl(int g, int n) {
    g = (g < 0) ? -g : g;
    return (g >= n) ? (2 * n - 2 - g) : g;
}

__device__ __forceinline__ float ex2(float x) {
    float r;
    asm("ex2.approx.ftz.f32 %0, %1;" : "=f"(r) : "f"(x));
    return r;
}

// One dx-pair (dxe, dxe+1) at one dy.
// RB  : row reflection for edge row-strips.
// LAST: hi component (dx = dxe+1) is out of range; screen may include it
//       (conservative) but the tail must not accumulate it.
template <bool RB, bool LAST>
__device__ __forceinline__ void nlm_pair(
    const float* __restrict__ Sf, const __half2* __restrict__ S2,
    const __half2* __restrict__ Cc2,
    float (&wacc)[16], float (&vacc)[16],
    int rw0, int r0m13, int colB, int colS, int dy, int dxe)
{
    const int cb = colB + dxe;
    const __half2* B = S2 + (dy - r0m13) * REG_W + cb;   // + qr*REG_W
    const float*  F = Sf + (dy - r0m13) * REG_W + colS + dxe;
    const __half  thr = __float2half(THR);

    __half2 d2[7];
    __half2 V2 = __float2half2_rn(0.0f);
    // warm-up rows j = rw0-3 .. rw0+2
    #pragma unroll
    for (int m = 0; m < 6; ++m) {
        int j = rw0 - 3 + m;
        int qr = RB ? refl(j, IMG_H) : j;
        __half2 bv = B[qr * REG_W];
        __half2 t  = __hsub2(Cc2[m], bv);
        d2[m] = __hmul2(t, t);
        V2 = __hadd2(V2, d2[m]);
    }
    // 4 quads of 4 rows
    #pragma unroll
    for (int q = 0; q < 4; ++q) {
        __half2 Vq[4];
        #pragma unroll
        for (int s = 0; s < 4; ++s) {
            int i = 4 * q + s;
            int j = rw0 + 3 + i;
            int qr = RB ? refl(j, IMG_H) : j;
            __half2 bv = B[qr * REG_W];
            __half2 t  = __hsub2(Cc2[i + 6], bv);
            __half2 dn = __hmul2(t, t);
            V2 = __hadd2(V2, dn);
            d2[(i + 6) % 7] = dn;
            Vq[s] = V2;
            V2 = __hsub2(V2, d2[i % 7]);
        }
        // screen: min over 8 values (4 rows x 2 dx)
        __half2 mn2 = __hmin2(__hmin2(Vq[0], Vq[1]), __hmin2(Vq[2], Vq[3]));
        __half mn = __hmin(__low2half(mn2), __high2half(mn2));
        unsigned msk = __ballot_sync(0xffffffffu, __hle(mn, thr));
        unsigned r = msk & (msk >> 1);
        r &= (r >> 2);
        r &= (r >> 3);                 // 7-consecutive-lane run
        if (r) {
            const int i0 = 4 * q;
            #pragma unroll
            for (int s = 0; s < 4; ++s) {
                __half2 h = Vq[s];
                __half2 a = __hadd2(h, __shfl_down_sync(0xffffffffu, h, 1));
                __half2 b2 = __hadd2(a, __shfl_down_sync(0xffffffffu, a, 2));
                __half2 s7 = __hadd2(b2,
                             __hadd2(__shfl_down_sync(0xffffffffu, a, 4),
                                     __shfl_down_sync(0xffffffffu, h, 6)));
                int i = i0 + s;
                const float* Fr = F + (rw0 + i) * REG_W;
                float wlo = ex2(-C2F * __low2float(s7));
                wacc[i] += wlo;
                vacc[i]  = fmaf(wlo, Fr[0], vacc[i]);
                if (!LAST) {
                    float whi = ex2(-C2F * __high2float(s7));
                    wacc[i] += whi;
                    vacc[i]  = fmaf(whi, Fr[1], vacc[i]);
                }
            }
        }
    }
}

template <bool RB>
__device__ __forceinline__ void nlm_accum(
    const float* __restrict__ Sf, const __half2* __restrict__ S2,
    const __half2* __restrict__ Cc2,
    float (&wacc)[16], float (&vacc)[16],
    int rw0, int r0m13, int colB, int colS)
{
    #pragma unroll 1
    for (int dy = -10; dy <= 10; ++dy) {
        #pragma unroll 1
        for (int p = 0; p < 10; ++p) {
            nlm_pair<RB, false>(Sf, S2, Cc2, wacc, vacc,
                                rw0, r0m13, colB, colS, dy, -10 + 2 * p);
        }
        nlm_pair<RB, true>(Sf, S2, Cc2, wacc, vacc,
                           rw0, r0m13, colB, colS, dy, 10);
    }
}

__global__ __launch_bounds__(NTHREADS, 2)
void nlm_kernel(const float* __restrict__ x, float* __restrict__ out) {
    extern __shared__ unsigned char smem_raw[];
    float* Sf = reinterpret_cast<float*>(smem_raw);
    __half2* S2 = reinterpret_cast<__half2*>(smem_raw + TILE_N * 4);

    const int b  = blockIdx.z;
    const int r0 = blockIdx.y * OUT_H;
    const int c0 = blockIdx.x * OUT_W;
    const int tid = threadIdx.x;

    // fp32 reflect-padded tile
    const float* xb = x + (size_t)b * (IMG_H * IMG_W);
    #pragma unroll 4
    for (int idx = tid; idx < TILE_N; idx += NTHREADS) {
        int i = idx / REG_W;
        int j = idx - i * REG_W;
        int gr = refl(r0 - 13 + i, IMG_H);
        int gc = refl(c0 - 13 + j, IMG_W);
        Sf[idx] = xb[gr * IMG_W + gc];
    }
    __syncthreads();

    // half2 pair tile: S2[j] = (half(Sf[j]), half(Sf[j+1]))
    #pragma unroll 4
    for (int idx = tid; idx < TILE_N; idx += NTHREADS) {
        int i = idx / REG_W;
        int j = idx - i * REG_W;
        int j1 = (j + 1 < REG_W) ? (j + 1) : j;
        S2[idx] = __floats2half2_rn(Sf[i * REG_W + j], Sf[i * REG_W + j1]);
    }
    __syncthreads();

    const int w = tid >> 5, l = tid & 31;
    const int wx = w & 3, wy = w >> 2;
    const int rw0 = r0 + wy * 16;
    const int c0w = c0 + wx * 26;
    const int u = c0w - 3 + l;
    const int qc = refl(u, IMG_W);
    const int r0m13 = r0 - 13;
    const int c0m13 = c0 - 13;
    const int colB = qc - c0m13;
    const int lclamp = (l < 26) ? l : 25;
    const int colS = (c0w + lclamp) - c0m13;

    // center-column cache as duplicated half2
    __half2 Cc2[22];
    #pragma unroll
    for (int m = 0; m < 22; ++m) {
        int qr = refl(rw0 - 3 + m, IMG_H);
        Cc2[m] = __float2half2_rn(Sf[(qr - r0m13) * REG_W + colB]);
    }

    float wacc[16], vacc[16];
    #pragma unroll
    for (int i = 0; i < 16; ++i) { wacc[i] = 0.0f; vacc[i] = 0.0f; }

    const bool rowRefl = (rw0 - 3 < 0) || (rw0 + 18 >= IMG_H);
    if (!rowRefl) {
        nlm_accum<false>(Sf, S2, Cc2, wacc, vacc, rw0, r0m13, colB, colS);
    } else {
        nlm_accum<true>(Sf, S2, Cc2, wacc, vacc, rw0, r0m13, colB, colS);
    }

    const int cout = c0w + l;
    if (l < 26 && cout < IMG_W) {
        float* ob = out + (size_t)b * (IMG_H * IMG_W);
        #pragma unroll
        for (int i = 0; i < 16; ++i) {
            float q = vacc[i] / wacc[i];
            q = fminf(fmaxf(q, 0.0f), 1.0f);
            ob[(rw0 + i) * IMG_W + cout] = q;
        }
    }
}

extern "C" void kernel_launch(void* const* d_in, const int* in_sizes, int n_in,
                              void* d_out, int out_size) {
    const float* x = (const float*)d_in[0];
    float* out = (float*)d_out;
    (void)in_sizes; (void)n_in; (void)out_size;

    cudaFuncSetAttribute(nlm_kernel,
                         cudaFuncAttributeMaxDynamicSharedMemorySize,
                         SMEM_BYTES);

    dim3 grid((IMG_W + OUT_W - 1) / OUT_W,   // 10
              IMG_H / OUT_H,                 // 32
              4);
    dim3 block(NTHREADS);
    nlm_kernel<<<grid, block, SMEM_BYTES>>>(x, out);
}